// round 15
// baseline (speedup 1.0000x reference)
#include <cuda_runtime.h>
#include <cuda_fp16.h>
#include <math.h>
#include <stdint.h>

#define B_SZ 8192
#define D_SZ 128
#define KA 144                           // augmented K (one extra k16 step)
#define KA_U (KA / 2)                    // 72 uints per row
#define TM 128
#define TN 128
#define S_STRIPS (B_SZ / TM)             // 64
#define TILES_TOT 2080
#define NCTA 148
#define BSTRIDE_H 152                    // padded smem row stride (halfs): 304B, conflict-free
#define A_ELEMS (TM * BSTRIDE_H)
#define B_ELEMS (TN * BSTRIDE_H)
#define CBIAS 128.0f                     // sq centering; d = 2*CBIAS - dist^2

__device__ __half   g_xa[B_SZ * KA];     // [sqrt2*x, sq', 1, 0...]
__device__ __half   g_xb[B_SZ * KA];     // [sqrt2*x, -1, -sq', 0...]
__device__ float    g_sq[B_SZ];
__device__ float    g_ce[B_SZ];
__device__ unsigned g_pm[B_SZ];          // encoded MIN of d over positives (init 0xFFFFFFFF)
__device__ unsigned g_pn[B_SZ];          // encoded MAX of d over negatives (init 0)
__device__ unsigned g_done;

// ---------------- helpers ----------------
__device__ __forceinline__ unsigned encf(float f) {
    unsigned u = __float_as_uint(f);
    return ((int)u < 0) ? ~u : (u | 0x80000000u);
}
__device__ __forceinline__ float decf(unsigned u) {
    return (u & 0x80000000u) ? __uint_as_float(u & 0x7fffffffu) : __uint_as_float(~u);
}
__device__ __forceinline__ void mma_f16(float d[4], const unsigned a[4],
                                        unsigned b0, unsigned b1) {
    asm volatile(
        "mma.sync.aligned.m16n8k16.row.col.f32.f16.f16.f32 "
        "{%0,%1,%2,%3}, {%4,%5,%6,%7}, {%8,%9}, {%0,%1,%2,%3};"
        : "+f"(d[0]), "+f"(d[1]), "+f"(d[2]), "+f"(d[3])
        : "r"(a[0]), "r"(a[1]), "r"(a[2]), "r"(a[3]), "r"(b0), "r"(b1));
}
__device__ __forceinline__ void ldsm_x4(unsigned& r0, unsigned& r1, unsigned& r2, unsigned& r3,
                                        unsigned addr) {
    asm volatile("ldmatrix.sync.aligned.m8n8.x4.shared.b16 {%0,%1,%2,%3}, [%4];"
                 : "=r"(r0), "=r"(r1), "=r"(r2), "=r"(r3) : "r"(addr));
}
__device__ __forceinline__ unsigned smem_u32(const void* p) {
    unsigned a;
    asm("{ .reg .u64 t; cvta.to.shared.u64 t, %1; cvt.u32.u64 %0, t; }" : "=r"(a) : "l"(p));
    return a;
}
__device__ __forceinline__ void cp16(unsigned dst, const void* src) {
    asm volatile("cp.async.cg.shared.global [%0], [%1], 16;" :: "r"(dst), "l"(src) : "memory");
}
#define CP_COMMIT() asm volatile("cp.async.commit_group;" ::: "memory")
#define CP_WAIT1()  asm volatile("cp.async.wait_group 1;" ::: "memory")
#define CP_WAIT0()  asm volatile("cp.async.wait_group 0;" ::: "memory")

// ---------- K1: sum-of-squares + CE + augmented fp16 copies + minmax init ----------
__global__ void rowstats_kernel(const float* __restrict__ logits, const void* __restrict__ targets) {
    __shared__ unsigned s_det[2];
    int tid = threadIdx.x;
    int lane = tid & 31;
    int wid = tid >> 5;
    int row = (blockIdx.x << 3) + wid;
    if (blockIdx.x == 0 && tid == 0) g_done = 0u;

    {
        unsigned dv = 0;
        if (tid < 64)
            dv = (unsigned)((const int*)targets)[2 * (((blockIdx.x << 3) + tid) & (B_SZ - 1)) + 1];
#pragma unroll
        for (int o = 16; o; o >>= 1) dv |= __shfl_xor_sync(0xffffffffu, dv, o);
        if (wid < 2 && lane == 0) s_det[wid] = dv;
    }
    float4 v = reinterpret_cast<const float4*>(logits)[row * 32 + lane];
    __syncthreads();
    const int is64 = ((s_det[0] | s_det[1]) == 0) ? 1 : 0;

    float ss = fmaf(v.x, v.x, fmaf(v.y, v.y, fmaf(v.z, v.z, v.w * v.w)));
    float mx = fmaxf(fmaxf(v.x, v.y), fmaxf(v.z, v.w));
#pragma unroll
    for (int o = 16; o; o >>= 1) {
        ss += __shfl_xor_sync(0xffffffffu, ss, o);
        mx = fmaxf(mx, __shfl_xor_sync(0xffffffffu, mx, o));
    }
    // augmented fp16 rows: x part scaled by sqrt(2)
    {
        const float R2 = 1.41421356237f;
        __half2 h0 = __floats2half2_rn(v.x * R2, v.y * R2);
        __half2 h1 = __floats2half2_rn(v.z * R2, v.w * R2);
        uint2 pk = make_uint2(*reinterpret_cast<unsigned*>(&h0), *reinterpret_cast<unsigned*>(&h1));
        reinterpret_cast<uint2*>(g_xa)[row * (KA_U / 2) + lane];   // (address calc below)
        unsigned* xa = reinterpret_cast<unsigned*>(g_xa) + row * KA_U;
        unsigned* xb = reinterpret_cast<unsigned*>(g_xb) + row * KA_U;
        xa[lane * 2] = pk.x; xa[lane * 2 + 1] = pk.y;
        xb[lane * 2] = pk.x; xb[lane * 2 + 1] = pk.y;
        float sqp = ss - CBIAS;
        if (lane == 0) {
            __half2 ta = __floats2half2_rn(sqp, 1.0f);
            __half2 tb = __floats2half2_rn(-1.0f, -sqp);
            xa[64] = *reinterpret_cast<unsigned*>(&ta);
            xb[64] = *reinterpret_cast<unsigned*>(&tb);
        }
        if (lane < 7) { xa[65 + lane] = 0u; xb[65 + lane] = 0u; }
    }
    float se = expf(v.x - mx) + expf(v.y - mx) + expf(v.z - mx) + expf(v.w - mx);
#pragma unroll
    for (int o = 16; o; o >>= 1) se += __shfl_xor_sync(0xffffffffu, se, o);
    int t = is64 ? (int)((const long long*)targets)[row] : ((const int*)targets)[row];
    int c = t & 3;
    float tv = (c == 0) ? v.x : (c == 1) ? v.y : (c == 2) ? v.z : v.w;
    tv = __shfl_sync(0xffffffffu, tv, t >> 2);
    if (lane == 0) {
        g_sq[row] = ss;
        g_ce[row] = mx + logf(se) - tv;
        g_pm[row] = 0xFFFFFFFFu;    // min-identity (encoded)
        g_pn[row] = 0u;             // max-identity (encoded)
    }
}

// ---------- K2: symmetric augmented-MMA Gram + mining + fused finalize ----------
// d = 2C - dist^2 comes straight out of the MMA. Hardest-pos = min d, hardest-neg = max d.
// 148 CTAs (occ 1): 2080 tiles = 148*14 + 8. Warp grid 2x4 (warp tile 64x32).
extern __shared__ __half s_all[];   // A: [0,A) ; B0: [A,A+B) ; B1: [A+B,A+2B)

__global__ void __launch_bounds__(256, 1)
triplet_mma_kernel(const void* __restrict__ targets, float* __restrict__ out) {
    __shared__ __align__(8) int s_tj[2][TN];
    __shared__ int    s_ta[TM];
    __shared__ double s_rt[8], s_rc[8];
    __shared__ int    s_last;
    __shared__ unsigned s_det;

    const int tid  = threadIdx.x;
    const int lane = tid & 31;
    const int wid  = tid >> 5;
    const int warp_m = (wid & 1) * 64;
    const int warp_n = (wid >> 1) * 32;
    const int g = lane >> 2, tq = lane & 3;
    const unsigned sbase = smem_u32(s_all);

    if (wid == 0) {
        unsigned dv = (unsigned)((const int*)targets)[2 * lane + 1]
                    | (unsigned)((const int*)targets)[2 * (lane + 32) + 1];
#pragma unroll
        for (int o = 16; o; o >>= 1) dv |= __shfl_xor_sync(0xffffffffu, dv, o);
        if (lane == 0) s_det = dv;
    }
    __syncthreads();
    const int is64 = (s_det == 0) ? 1 : 0;

    const unsigned a_lm = sbase + (unsigned)((warp_m + (lane & 15)) * BSTRIDE_H + (lane >> 4) * 8) * 2u;
    const unsigned b_lm_off = (unsigned)((warp_n + (lane & 7) + 8 * (lane >> 4)) * BSTRIDE_H
                                         + ((lane >> 3) & 1) * 8) * 2u;

    // ---- tile range: 2080 = 148*14 + 8 ----
    const int bx = blockIdx.x;
    const int my_tpc = 14 + (bx < 8 ? 1 : 0);
    int T0 = bx * 14 + (bx < 8 ? bx : 8);
    int ti = 0, rem = T0;
    while (rem >= S_STRIPS - ti) { rem -= S_STRIPS - ti; ti++; }
    int tj = ti + rem;

    __half* s_a = s_all;

    {
        const uint4* Xu = reinterpret_cast<const uint4*>(g_xa);
        for (int e = tid; e < TM * 18; e += 256) {
            int n = e / 18, q = e - n * 18;
            *reinterpret_cast<uint4*>(&s_a[n * BSTRIDE_H + q * 8]) = Xu[(ti * TM + n) * 18 + q];
        }
        if (tid < TM) {
            int r = ti * TM + tid;
            s_ta[tid] = is64 ? (int)((const long long*)targets)[r] : ((const int*)targets)[r];
        }
    }
    {
        int j0 = tj * TN;
        unsigned sb = sbase + (unsigned)A_ELEMS * 2u;
        for (int e = tid; e < TN * 18; e += 256) {
            int n = e / 18, q = e - n * 18;
            cp16(sb + (unsigned)(n * BSTRIDE_H + q * 8) * 2u, &g_xb[(j0 + n) * KA + q * 8]);
        }
        if (tid < TN)
            s_tj[0][tid] = is64 ? (int)((const long long*)targets)[j0 + tid]
                                : ((const int*)targets)[j0 + tid];
        CP_COMMIT();
    }
    __syncthreads();

    int ta2[4][2];
    int reg_i = ti;
#pragma unroll
    for (int mf = 0; mf < 4; mf++)
#pragma unroll
        for (int h = 0; h < 2; h++)
            ta2[mf][h] = s_ta[warp_m + mf * 16 + g + 8 * h];

    // runm: MIN d over positives (init +inf). runn: MAX d over negatives (init -inf).
    float runm[8], runn[8];
#pragma unroll
    for (int s = 0; s < 8; s++) { runm[s] = INFINITY; runn[s] = -INFINITY; }

    for (int t = 0; t < my_tpc; t++) {
        const int cur = t & 1, nxt = cur ^ 1;
        int ni = ti, nj = tj + 1;
        if (nj == S_STRIPS) { ni = ti + 1; nj = ni; }
        const bool last = (t == my_tpc - 1);
        const bool rowchg = (!last) && (ni != ti);
        const bool diag = (ti == tj);

        if (reg_i != ti) {
            reg_i = ti;
#pragma unroll
            for (int mf = 0; mf < 4; mf++)
#pragma unroll
                for (int h = 0; h < 2; h++)
                    ta2[mf][h] = s_ta[warp_m + mf * 16 + g + 8 * h];
        }

        if (!last) {
            int j0 = nj * TN;
            unsigned sb = sbase + (unsigned)(A_ELEMS + nxt * B_ELEMS) * 2u;
            for (int e = tid; e < TN * 18; e += 256) {
                int n = e / 18, q = e - n * 18;
                cp16(sb + (unsigned)(n * BSTRIDE_H + q * 8) * 2u, &g_xb[(j0 + n) * KA + q * 8]);
            }
            if (tid < TN)
                s_tj[nxt][tid] = is64 ? (int)((const long long*)targets)[j0 + tid]
                                      : ((const int*)targets)[j0 + tid];
            CP_COMMIT();
            CP_WAIT1();
        } else {
            CP_WAIT0();
        }
        __syncthreads();

        // ---- MMA 64x32 warp tile over K=144 (9 k16 steps) ----
        float d[4][4][4];
#pragma unroll
        for (int mf = 0; mf < 4; mf++)
#pragma unroll
            for (int nf = 0; nf < 4; nf++)
#pragma unroll
                for (int r = 0; r < 4; r++) d[mf][nf][r] = 0.0f;

        const unsigned b_lm = sbase + (unsigned)(A_ELEMS + cur * B_ELEMS) * 2u + b_lm_off;
#pragma unroll
        for (int s = 0; s < 9; s++) {
            unsigned af[4][4];
#pragma unroll
            for (int mf = 0; mf < 4; mf++)
                ldsm_x4(af[mf][0], af[mf][1], af[mf][2], af[mf][3],
                        a_lm + mf * (16 * BSTRIDE_H * 2) + s * 32);
            unsigned bf[4][2];
#pragma unroll
            for (int u = 0; u < 2; u++)
                ldsm_x4(bf[2 * u][0], bf[2 * u][1], bf[2 * u + 1][0], bf[2 * u + 1][1],
                        b_lm + u * (16 * BSTRIDE_H * 2) + s * 32);
#pragma unroll
            for (int mf = 0; mf < 4; mf++)
#pragma unroll
                for (int nf = 0; nf < 4; nf++)
                    mma_f16(d[mf][nf], af[mf], bf[nf][0], bf[nf][1]);
        }

        // ---- two-sided epilogue on raw d (no FMA); col side skipped on diagonal ----
        const int j0 = tj * TN;
#pragma unroll
        for (int nf = 0; nf < 4; nf++) {
            int colp = warp_n + nf * 8 + 2 * tq;
            int2 tt = *reinterpret_cast<const int2*>(&s_tj[cur][colp]);
            if (!diag) {
                float cm0 = INFINITY, cm1 = INFINITY, cn0 = -INFINITY, cn1 = -INFINITY;
#pragma unroll
                for (int mf = 0; mf < 4; mf++) {
                    int s0 = 2 * mf, s1 = 2 * mf + 1;
                    float d0 = d[mf][nf][0], d1 = d[mf][nf][1];
                    float d2 = d[mf][nf][2], d3 = d[mf][nf][3];
                    if (tt.x == ta2[mf][0]) { runm[s0] = fminf(runm[s0], d0); cm0 = fminf(cm0, d0); }
                    else                    { runn[s0] = fmaxf(runn[s0], d0); cn0 = fmaxf(cn0, d0); }
                    if (tt.y == ta2[mf][0]) { runm[s0] = fminf(runm[s0], d1); cm1 = fminf(cm1, d1); }
                    else                    { runn[s0] = fmaxf(runn[s0], d1); cn1 = fmaxf(cn1, d1); }
                    if (tt.x == ta2[mf][1]) { runm[s1] = fminf(runm[s1], d2); cm0 = fminf(cm0, d2); }
                    else                    { runn[s1] = fmaxf(runn[s1], d2); cn0 = fmaxf(cn0, d2); }
                    if (tt.y == ta2[mf][1]) { runm[s1] = fminf(runm[s1], d3); cm1 = fminf(cm1, d3); }
                    else                    { runn[s1] = fmaxf(runn[s1], d3); cn1 = fmaxf(cn1, d3); }
                }
                cm0 = fminf(cm0, __shfl_xor_sync(0xffffffffu, cm0, 4));
                cm0 = fminf(cm0, __shfl_xor_sync(0xffffffffu, cm0, 8));
                cm0 = fminf(cm0, __shfl_xor_sync(0xffffffffu, cm0, 16));
                cn0 = fmaxf(cn0, __shfl_xor_sync(0xffffffffu, cn0, 4));
                cn0 = fmaxf(cn0, __shfl_xor_sync(0xffffffffu, cn0, 8));
                cn0 = fmaxf(cn0, __shfl_xor_sync(0xffffffffu, cn0, 16));
                cm1 = fminf(cm1, __shfl_xor_sync(0xffffffffu, cm1, 4));
                cm1 = fminf(cm1, __shfl_xor_sync(0xffffffffu, cm1, 8));
                cm1 = fminf(cm1, __shfl_xor_sync(0xffffffffu, cm1, 16));
                cn1 = fmaxf(cn1, __shfl_xor_sync(0xffffffffu, cn1, 4));
                cn1 = fmaxf(cn1, __shfl_xor_sync(0xffffffffu, cn1, 8));
                cn1 = fmaxf(cn1, __shfl_xor_sync(0xffffffffu, cn1, 16));
                if (lane < 4) {
                    int gc = j0 + warp_n + nf * 8 + 2 * lane;
                    atomicMin(&g_pm[gc], encf(cm0));
                    atomicMax(&g_pn[gc], encf(cn0));
                    atomicMin(&g_pm[gc + 1], encf(cm1));
                    atomicMax(&g_pn[gc + 1], encf(cn1));
                }
            } else {
#pragma unroll
                for (int mf = 0; mf < 4; mf++) {
                    int s0 = 2 * mf, s1 = 2 * mf + 1;
                    float d0 = d[mf][nf][0], d1 = d[mf][nf][1];
                    float d2 = d[mf][nf][2], d3 = d[mf][nf][3];
                    if (tt.x == ta2[mf][0]) runm[s0] = fminf(runm[s0], d0);
                    else                    runn[s0] = fmaxf(runn[s0], d0);
                    if (tt.y == ta2[mf][0]) runm[s0] = fminf(runm[s0], d1);
                    else                    runn[s0] = fmaxf(runn[s0], d1);
                    if (tt.x == ta2[mf][1]) runm[s1] = fminf(runm[s1], d2);
                    else                    runn[s1] = fmaxf(runn[s1], d2);
                    if (tt.y == ta2[mf][1]) runm[s1] = fminf(runm[s1], d3);
                    else                    runn[s1] = fmaxf(runn[s1], d3);
                }
            }
        }

        // ---- row flush on strip change / end ----
        if (last || rowchg) {
            const int i0 = ti * TM;
#pragma unroll
            for (int slot = 0; slot < 8; slot++) {
                float m = runm[slot], n = runn[slot];
                m = fminf(m, __shfl_xor_sync(0xffffffffu, m, 1));
                m = fminf(m, __shfl_xor_sync(0xffffffffu, m, 2));
                n = fmaxf(n, __shfl_xor_sync(0xffffffffu, n, 1));
                n = fmaxf(n, __shfl_xor_sync(0xffffffffu, n, 2));
                if (tq == 0) {
                    int r = i0 + warp_m + (slot >> 1) * 16 + g + 8 * (slot & 1);
                    atomicMin(&g_pm[r], encf(m));
                    atomicMax(&g_pn[r], encf(n));
                }
                runm[slot] = INFINITY; runn[slot] = -INFINITY;
            }
        }
        if (rowchg) {
            __syncthreads();
            const uint4* Xu = reinterpret_cast<const uint4*>(g_xa);
            for (int e = tid; e < TM * 18; e += 256) {
                int n = e / 18, q = e - n * 18;
                *reinterpret_cast<uint4*>(&s_a[n * BSTRIDE_H + q * 8]) = Xu[(ni * TM + n) * 18 + q];
            }
            if (tid < TM) {
                int r = ni * TM + tid;
                s_ta[tid] = is64 ? (int)((const long long*)targets)[r] : ((const int*)targets)[r];
            }
        }
        __syncthreads();
        ti = ni; tj = nj;
    }

    // ---- last-CTA fused finalize ----
    if (tid == 0) {
        __threadfence();
        unsigned tk = atomicAdd(&g_done, 1u);
        s_last = (tk == NCTA - 1) ? 1 : 0;
    }
    __syncthreads();
    if (s_last) {
        __threadfence();
        double st = 0.0, sc = 0.0;
#pragma unroll
        for (int a = tid; a < B_SZ; a += 256) {
            float dp = decf(g_pm[a]);   // min d over positives -> hardest pos
            float dn = decf(g_pn[a]);   // max d over negatives -> hardest neg
            float dap = sqrtf(fmaxf(2.0f * CBIAS - dp, 1e-12f));
            float dan = sqrtf(fmaxf(2.0f * CBIAS - dn, 1e-12f));
            st += (double)fmaxf(dap - dan + 0.3f, 0.0f);
            sc += (double)g_ce[a];
        }
#pragma unroll
        for (int o = 16; o; o >>= 1) {
            st += __shfl_down_sync(0xffffffffu, st, o);
            sc += __shfl_down_sync(0xffffffffu, sc, o);
        }
        if (lane == 0) { s_rt[wid] = st; s_rc[wid] = sc; }
        __syncthreads();
        if (tid == 0) {
            double t0 = 0.0, c0 = 0.0;
#pragma unroll
            for (int w = 0; w < 8; w++) { t0 += s_rt[w]; c0 += s_rc[w]; }
            const float LAM = 0.25f;
            const float TAU = logf(128.0f);
            float ce = (float)(c0 / (double)B_SZ);
            float l  = (float)(t0 / (double)B_SZ);
            float e1 = expf(1.0f);
            float z = 0.5f * fmaxf(-2.0f / e1, (l - TAU) / LAM);
            float pv = sqrtf(fmaxf(2.0f * (e1 * z + 1.0f), 0.0f));
            float wn = -1.0f + pv - pv * pv * (1.0f / 3.0f) + (11.0f / 72.0f) * pv * pv * pv;
            float w = (z < 0.0f) ? wn : log1pf(fmaxf(z, 0.0f));
#pragma unroll
            for (int it = 0; it < 8; it++) {
                float ew = expf(w);
                float f = fmaf(w, ew, -z);
                float wp1 = w + 1.0f;
                w = w - f / (ew * wp1 - (w + 2.0f) * f / (2.0f * wp1));
            }
            float sigma = expf(-w);
            float ls = logf(sigma);
            float loss = (ce - TAU) * sigma + LAM * ls * ls;
            out[0] = loss / (float)B_SZ;
        }
    }
}

extern "C" void kernel_launch(void* const* d_in, const int* in_sizes, int n_in,
                              void* d_out, int out_size) {
    const float* logits = (const float*)d_in[0];
    const void* targets = d_in[1];
    float* out = (float*)d_out;
    (void)in_sizes; (void)n_in; (void)out_size;

    const int smem_bytes = (A_ELEMS + 2 * B_ELEMS) * (int)sizeof(__half);   // 116736
    cudaFuncSetAttribute(triplet_mma_kernel, cudaFuncAttributeMaxDynamicSharedMemorySize,
                         smem_bytes);

    rowstats_kernel<<<B_SZ / 8, 256>>>(logits, targets);
    triplet_mma_kernel<<<NCTA, 256, smem_bytes>>>(targets, out);
}

// round 16
// speedup vs baseline: 1.1729x; 1.1729x over previous
#include <cuda_runtime.h>
#include <cuda_fp16.h>
#include <math.h>
#include <stdint.h>

#define B_SZ 8192
#define D_SZ 128
#define TM 128
#define TN 128
#define S_STRIPS (B_SZ / TM)             // 64
#define TILES_TOT 2080
#define NCTA 296                         // 2 CTAs / SM
#define BSTRIDE_H 136
#define A_ELEMS (TM * BSTRIDE_H)
#define B_ELEMS (TN * BSTRIDE_H)
#define CBIAS 128.0f                     // d = 2*CBIAS - dist^2

__device__ __half   g_xh[B_SZ * D_SZ];   // sqrt(2)-scaled fp16 copy of logits
__device__ unsigned g_auga[B_SZ];        // packed half2 (sq - C, 1)
__device__ unsigned g_augb[B_SZ];        // packed half2 (-1, C - sq)
__device__ float    g_sq[B_SZ];
__device__ float    g_ce[B_SZ];
__device__ unsigned g_pm[B_SZ];          // encoded MIN d over positives (init 0xFFFFFFFF)
__device__ unsigned g_pn[B_SZ];          // encoded MAX d over negatives (init 0)
__device__ unsigned g_done;

// ---------------- helpers ----------------
__device__ __forceinline__ unsigned encf(float f) {
    unsigned u = __float_as_uint(f);
    return ((int)u < 0) ? ~u : (u | 0x80000000u);
}
__device__ __forceinline__ float decf(unsigned u) {
    return (u & 0x80000000u) ? __uint_as_float(u & 0x7fffffffu) : __uint_as_float(~u);
}
__device__ __forceinline__ void mma_f16(float d[4], const unsigned a[4],
                                        unsigned b0, unsigned b1) {
    asm volatile(
        "mma.sync.aligned.m16n8k16.row.col.f32.f16.f16.f32 "
        "{%0,%1,%2,%3}, {%4,%5,%6,%7}, {%8,%9}, {%0,%1,%2,%3};"
        : "+f"(d[0]), "+f"(d[1]), "+f"(d[2]), "+f"(d[3])
        : "r"(a[0]), "r"(a[1]), "r"(a[2]), "r"(a[3]), "r"(b0), "r"(b1));
}
__device__ __forceinline__ void ldsm_x4(unsigned& r0, unsigned& r1, unsigned& r2, unsigned& r3,
                                        unsigned addr) {
    asm volatile("ldmatrix.sync.aligned.m8n8.x4.shared.b16 {%0,%1,%2,%3}, [%4];"
                 : "=r"(r0), "=r"(r1), "=r"(r2), "=r"(r3) : "r"(addr));
}
__device__ __forceinline__ unsigned smem_u32(const void* p) {
    unsigned a;
    asm("{ .reg .u64 t; cvta.to.shared.u64 t, %1; cvt.u32.u64 %0, t; }" : "=r"(a) : "l"(p));
    return a;
}
__device__ __forceinline__ void cp16(unsigned dst, const void* src) {
    asm volatile("cp.async.cg.shared.global [%0], [%1], 16;" :: "r"(dst), "l"(src) : "memory");
}
#define CP_COMMIT() asm volatile("cp.async.commit_group;" ::: "memory")
#define CP_WAIT1()  asm volatile("cp.async.wait_group 1;" ::: "memory")
#define CP_WAIT0()  asm volatile("cp.async.wait_group 0;" ::: "memory")

// ---------- K1: sum-of-squares + CE + scaled fp16 copy + aug tables + init ----------
__global__ void rowstats_kernel(const float* __restrict__ logits, const void* __restrict__ targets) {
    __shared__ unsigned s_det[2];
    int tid = threadIdx.x;
    int lane = tid & 31;
    int wid = tid >> 5;
    int row = (blockIdx.x << 3) + wid;
    if (blockIdx.x == 0 && tid == 0) g_done = 0u;

    {
        unsigned dv = 0;
        if (tid < 64)
            dv = (unsigned)((const int*)targets)[2 * (((blockIdx.x << 3) + tid) & (B_SZ - 1)) + 1];
#pragma unroll
        for (int o = 16; o; o >>= 1) dv |= __shfl_xor_sync(0xffffffffu, dv, o);
        if (wid < 2 && lane == 0) s_det[wid] = dv;
    }
    float4 v = reinterpret_cast<const float4*>(logits)[row * 32 + lane];
    {
        const float R2 = 1.41421356237f;
        __half2 h0 = __floats2half2_rn(v.x * R2, v.y * R2);
        __half2 h1 = __floats2half2_rn(v.z * R2, v.w * R2);
        reinterpret_cast<uint2*>(g_xh)[row * 32 + lane] =
            make_uint2(*reinterpret_cast<unsigned*>(&h0), *reinterpret_cast<unsigned*>(&h1));
    }
    __syncthreads();
    const int is64 = ((s_det[0] | s_det[1]) == 0) ? 1 : 0;

    float ss = fmaf(v.x, v.x, fmaf(v.y, v.y, fmaf(v.z, v.z, v.w * v.w)));
    float mx = fmaxf(fmaxf(v.x, v.y), fmaxf(v.z, v.w));
#pragma unroll
    for (int o = 16; o; o >>= 1) {
        ss += __shfl_xor_sync(0xffffffffu, ss, o);
        mx = fmaxf(mx, __shfl_xor_sync(0xffffffffu, mx, o));
    }
    float se = expf(v.x - mx) + expf(v.y - mx) + expf(v.z - mx) + expf(v.w - mx);
#pragma unroll
    for (int o = 16; o; o >>= 1) se += __shfl_xor_sync(0xffffffffu, se, o);
    int t = is64 ? (int)((const long long*)targets)[row] : ((const int*)targets)[row];
    int c = t & 3;
    float tv = (c == 0) ? v.x : (c == 1) ? v.y : (c == 2) ? v.z : v.w;
    tv = __shfl_sync(0xffffffffu, tv, t >> 2);
    if (lane == 0) {
        float sqp = ss - CBIAS;
        __half2 ha = __floats2half2_rn(sqp, 1.0f);
        __half2 hb = __floats2half2_rn(-1.0f, -sqp);
        g_auga[row] = *reinterpret_cast<unsigned*>(&ha);
        g_augb[row] = *reinterpret_cast<unsigned*>(&hb);
        g_sq[row] = ss;
        g_ce[row] = mx + logf(se) - tv;
        g_pm[row] = 0xFFFFFFFFu;    // min-identity (encoded)
        g_pn[row] = 0u;             // max-identity (encoded)
    }
}

// ---------- K2: symmetric MMA Gram with in-MMA sq folding + mining + finalize ----------
// d = 2C - dist^2 straight from the accumulator (K=128 data steps + 1 register-aug step).
// 296 CTAs (occ 2): 2080 tiles = 296*7 + 8. Warp grid 2x4 (warp tile 64x32).
extern __shared__ __half s_all[];   // A: [0,A) ; B0: [A,A+B) ; B1: [A+B,A+2B)

__global__ void __launch_bounds__(256, 2)
triplet_mma_kernel(const void* __restrict__ targets, float* __restrict__ out) {
    __shared__ __align__(16) uint2 s_sjt[2][TN];   // {augb_j packed, t_j}
    __shared__ int      s_ta[TM];
    __shared__ unsigned s_auga[TM];
    __shared__ double   s_rt[8], s_rc[8];
    __shared__ int      s_last;
    __shared__ unsigned s_det;

    const int tid  = threadIdx.x;
    const int lane = tid & 31;
    const int wid  = tid >> 5;
    const int warp_m = (wid & 1) * 64;
    const int warp_n = (wid >> 1) * 32;
    const int g = lane >> 2, tq = lane & 3;
    const unsigned sbase = smem_u32(s_all);

    if (wid == 0) {
        unsigned dv = (unsigned)((const int*)targets)[2 * lane + 1]
                    | (unsigned)((const int*)targets)[2 * (lane + 32) + 1];
#pragma unroll
        for (int o = 16; o; o >>= 1) dv |= __shfl_xor_sync(0xffffffffu, dv, o);
        if (lane == 0) s_det = dv;
    }
    __syncthreads();
    const int is64 = (s_det == 0) ? 1 : 0;

    const unsigned a_lm = sbase + (unsigned)((warp_m + (lane & 15)) * BSTRIDE_H + (lane >> 4) * 8) * 2u;
    const unsigned b_lm_off = (unsigned)((warp_n + (lane & 7) + 8 * (lane >> 4)) * BSTRIDE_H
                                         + ((lane >> 3) & 1) * 8) * 2u;

    // ---- tile range: 2080 = 296*7 + 8 ----
    const int bx = blockIdx.x;
    const int my_tpc = 7 + (bx < 8 ? 1 : 0);
    int T0 = bx * 7 + (bx < 8 ? bx : 8);
    int ti = 0, rem = T0;
    while (rem >= S_STRIPS - ti) { rem -= S_STRIPS - ti; ti++; }
    int tj = ti + rem;

    __half* s_a = s_all;

    {
        const uint4* Xu = reinterpret_cast<const uint4*>(g_xh);
        for (int e = tid; e < TM * 16; e += 256) {
            int n = e >> 4, q = e & 15;
            *reinterpret_cast<uint4*>(&s_a[n * BSTRIDE_H + q * 8]) = Xu[(ti * TM + n) * 16 + q];
        }
        if (tid < TM) {
            int r = ti * TM + tid;
            s_ta[tid] = is64 ? (int)((const long long*)targets)[r] : ((const int*)targets)[r];
            s_auga[tid] = g_auga[r];
        }
    }
    {
        int j0 = tj * TN;
        unsigned sb = sbase + (unsigned)A_ELEMS * 2u;
        for (int e = tid; e < TN * 16; e += 256) {
            int n = e >> 4, q = e & 15;
            cp16(sb + (unsigned)(n * BSTRIDE_H + q * 8) * 2u, &g_xh[(j0 + n) * D_SZ + q * 8]);
        }
        if (tid < TN) {
            int t = is64 ? (int)((const long long*)targets)[j0 + tid]
                         : ((const int*)targets)[j0 + tid];
            s_sjt[0][tid] = make_uint2(g_augb[j0 + tid], (unsigned)t);
        }
        CP_COMMIT();
    }
    __syncthreads();

    int      ta2[4][2];
    unsigned auga[4][2];   // packed (sq'-C,1) for rows g / g+8 per mf; only tq==0 nonzero
    int reg_i = ti;
#pragma unroll
    for (int mf = 0; mf < 4; mf++)
#pragma unroll
        for (int h = 0; h < 2; h++) {
            int r = warp_m + mf * 16 + g + 8 * h;
            ta2[mf][h] = s_ta[r];
            auga[mf][h] = (tq == 0) ? s_auga[r] : 0u;
        }

    // runm: MIN d over positives; runn: MAX d over negatives
    float runm[8], runn[8];
#pragma unroll
    for (int s = 0; s < 8; s++) { runm[s] = INFINITY; runn[s] = -INFINITY; }

    for (int t = 0; t < my_tpc; t++) {
        const int cur = t & 1, nxt = cur ^ 1;
        int ni = ti, nj = tj + 1;
        if (nj == S_STRIPS) { ni = ti + 1; nj = ni; }
        const bool last = (t == my_tpc - 1);
        const bool rowchg = (!last) && (ni != ti);
        const bool diag = (ti == tj);

        if (reg_i != ti) {
            reg_i = ti;
#pragma unroll
            for (int mf = 0; mf < 4; mf++)
#pragma unroll
                for (int h = 0; h < 2; h++) {
                    int r = warp_m + mf * 16 + g + 8 * h;
                    ta2[mf][h] = s_ta[r];
                    auga[mf][h] = (tq == 0) ? s_auga[r] : 0u;
                }
        }

        if (!last) {
            int j0 = nj * TN;
            unsigned sb = sbase + (unsigned)(A_ELEMS + nxt * B_ELEMS) * 2u;
            for (int e = tid; e < TN * 16; e += 256) {
                int n = e >> 4, q = e & 15;
                cp16(sb + (unsigned)(n * BSTRIDE_H + q * 8) * 2u, &g_xh[(j0 + n) * D_SZ + q * 8]);
            }
            if (tid < TN) {
                int tt = is64 ? (int)((const long long*)targets)[j0 + tid]
                              : ((const int*)targets)[j0 + tid];
                s_sjt[nxt][tid] = make_uint2(g_augb[j0 + tid], (unsigned)tt);
            }
            CP_COMMIT();
            CP_WAIT1();
        } else {
            CP_WAIT0();
        }
        __syncthreads();

        // ---- MMA 64x32 warp tile: 8 data k-steps + 1 register-aug step ----
        float d[4][4][4];
#pragma unroll
        for (int mf = 0; mf < 4; mf++)
#pragma unroll
            for (int nf = 0; nf < 4; nf++)
#pragma unroll
                for (int r = 0; r < 4; r++) d[mf][nf][r] = 0.0f;

        const unsigned b_lm = sbase + (unsigned)(A_ELEMS + cur * B_ELEMS) * 2u + b_lm_off;
#pragma unroll
        for (int s = 0; s < 8; s++) {
            unsigned af[4][4];
#pragma unroll
            for (int mf = 0; mf < 4; mf++)
                ldsm_x4(af[mf][0], af[mf][1], af[mf][2], af[mf][3],
                        a_lm + mf * (16 * BSTRIDE_H * 2) + s * 32);
            unsigned bf[4][2];
#pragma unroll
            for (int u = 0; u < 2; u++)
                ldsm_x4(bf[2 * u][0], bf[2 * u][1], bf[2 * u + 1][0], bf[2 * u + 1][1],
                        b_lm + u * (16 * BSTRIDE_H * 2) + s * 32);
#pragma unroll
            for (int mf = 0; mf < 4; mf++)
#pragma unroll
                for (int nf = 0; nf < 4; nf++)
                    mma_f16(d[mf][nf], af[mf], bf[nf][0], bf[nf][1]);
        }
        // aug step: folds -(sq_i + sq_j) + 2C into the accumulator
        {
            unsigned baug[4];
#pragma unroll
            for (int nf = 0; nf < 4; nf++)
                baug[nf] = (tq == 0) ? s_sjt[cur][warp_n + nf * 8 + g].x : 0u;
#pragma unroll
            for (int mf = 0; mf < 4; mf++) {
                unsigned aA[4] = {auga[mf][0], auga[mf][1], 0u, 0u};
#pragma unroll
                for (int nf = 0; nf < 4; nf++)
                    mma_f16(d[mf][nf], aA, baug[nf], 0u);
            }
        }

        // ---- epilogue on raw d (no FMA); col side skipped on diagonal ----
        const int j0 = tj * TN;
#pragma unroll
        for (int nf = 0; nf < 4; nf++) {
            int colp = warp_n + nf * 8 + 2 * tq;
            uint4 pjt = *reinterpret_cast<const uint4*>(&s_sjt[cur][colp]);
            int t0 = (int)pjt.y, t1 = (int)pjt.w;
            if (!diag) {
                float cm0 = INFINITY, cm1 = INFINITY, cn0 = -INFINITY, cn1 = -INFINITY;
#pragma unroll
                for (int mf = 0; mf < 4; mf++) {
                    int s0 = 2 * mf, s1 = 2 * mf + 1;
                    float d0 = d[mf][nf][0], d1 = d[mf][nf][1];
                    float d2 = d[mf][nf][2], d3 = d[mf][nf][3];
                    if (t0 == ta2[mf][0]) { runm[s0] = fminf(runm[s0], d0); cm0 = fminf(cm0, d0); }
                    else                  { runn[s0] = fmaxf(runn[s0], d0); cn0 = fmaxf(cn0, d0); }
                    if (t1 == ta2[mf][0]) { runm[s0] = fminf(runm[s0], d1); cm1 = fminf(cm1, d1); }
                    else                  { runn[s0] = fmaxf(runn[s0], d1); cn1 = fmaxf(cn1, d1); }
                    if (t0 == ta2[mf][1]) { runm[s1] = fminf(runm[s1], d2); cm0 = fminf(cm0, d2); }
                    else                  { runn[s1] = fmaxf(runn[s1], d2); cn0 = fmaxf(cn0, d2); }
                    if (t1 == ta2[mf][1]) { runm[s1] = fminf(runm[s1], d3); cm1 = fminf(cm1, d3); }
                    else                  { runn[s1] = fmaxf(runn[s1], d3); cn1 = fmaxf(cn1, d3); }
                }
                cm0 = fminf(cm0, __shfl_xor_sync(0xffffffffu, cm0, 4));
                cm0 = fminf(cm0, __shfl_xor_sync(0xffffffffu, cm0, 8));
                cm0 = fminf(cm0, __shfl_xor_sync(0xffffffffu, cm0, 16));
                cn0 = fmaxf(cn0, __shfl_xor_sync(0xffffffffu, cn0, 4));
                cn0 = fmaxf(cn0, __shfl_xor_sync(0xffffffffu, cn0, 8));
                cn0 = fmaxf(cn0, __shfl_xor_sync(0xffffffffu, cn0, 16));
                cm1 = fminf(cm1, __shfl_xor_sync(0xffffffffu, cm1, 4));
                cm1 = fminf(cm1, __shfl_xor_sync(0xffffffffu, cm1, 8));
                cm1 = fminf(cm1, __shfl_xor_sync(0xffffffffu, cm1, 16));
                cn1 = fmaxf(cn1, __shfl_xor_sync(0xffffffffu, cn1, 4));
                cn1 = fmaxf(cn1, __shfl_xor_sync(0xffffffffu, cn1, 8));
                cn1 = fmaxf(cn1, __shfl_xor_sync(0xffffffffu, cn1, 16));
                if (lane < 4) {
                    int gc = j0 + warp_n + nf * 8 + 2 * lane;
                    atomicMin(&g_pm[gc], encf(cm0));
                    atomicMax(&g_pn[gc], encf(cn0));
                    atomicMin(&g_pm[gc + 1], encf(cm1));
                    atomicMax(&g_pn[gc + 1], encf(cn1));
                }
            } else {
#pragma unroll
                for (int mf = 0; mf < 4; mf++) {
                    int s0 = 2 * mf, s1 = 2 * mf + 1;
                    float d0 = d[mf][nf][0], d1 = d[mf][nf][1];
                    float d2 = d[mf][nf][2], d3 = d[mf][nf][3];
                    if (t0 == ta2[mf][0]) runm[s0] = fminf(runm[s0], d0);
                    else                  runn[s0] = fmaxf(runn[s0], d0);
                    if (t1 == ta2[mf][0]) runm[s0] = fminf(runm[s0], d1);
                    else                  runn[s0] = fmaxf(runn[s0], d1);
                    if (t0 == ta2[mf][1]) runm[s1] = fminf(runm[s1], d2);
                    else                  runn[s1] = fmaxf(runn[s1], d2);
                    if (t1 == ta2[mf][1]) runm[s1] = fminf(runm[s1], d3);
                    else                  runn[s1] = fmaxf(runn[s1], d3);
                }
            }
        }

        // ---- row flush on strip change / end ----
        if (last || rowchg) {
            const int i0 = ti * TM;
#pragma unroll
            for (int slot = 0; slot < 8; slot++) {
                float m = runm[slot], n = runn[slot];
                m = fminf(m, __shfl_xor_sync(0xffffffffu, m, 1));
                m = fminf(m, __shfl_xor_sync(0xffffffffu, m, 2));
                n = fmaxf(n, __shfl_xor_sync(0xffffffffu, n, 1));
                n = fmaxf(n, __shfl_xor_sync(0xffffffffu, n, 2));
                if (tq == 0) {
                    int r = i0 + warp_m + (slot >> 1) * 16 + g + 8 * (slot & 1);
                    atomicMin(&g_pm[r], encf(m));
                    atomicMax(&g_pn[r], encf(n));
                }
                runm[slot] = INFINITY; runn[slot] = -INFINITY;
            }
        }
        if (rowchg) {
            __syncthreads();
            const uint4* Xu = reinterpret_cast<const uint4*>(g_xh);
            for (int e = tid; e < TM * 16; e += 256) {
                int n = e >> 4, q = e & 15;
                *reinterpret_cast<uint4*>(&s_a[n * BSTRIDE_H + q * 8]) = Xu[(ni * TM + n) * 16 + q];
            }
            if (tid < TM) {
                int r = ni * TM + tid;
                s_ta[tid] = is64 ? (int)((const long long*)targets)[r] : ((const int*)targets)[r];
                s_auga[tid] = g_auga[r];
            }
        }
        __syncthreads();
        ti = ni; tj = nj;
    }

    // ---- last-CTA fused finalize ----
    if (tid == 0) {
        __threadfence();
        unsigned tk = atomicAdd(&g_done, 1u);
        s_last = (tk == NCTA - 1) ? 1 : 0;
    }
    __syncthreads();
    if (s_last) {
        __threadfence();
        double st = 0.0, sc = 0.0;
#pragma unroll
        for (int a = tid; a < B_SZ; a += 256) {
            float dp = decf(g_pm[a]);   // min d over positives  -> hardest positive
            float dn = decf(g_pn[a]);   // max d over negatives  -> hardest negative
            float dap = sqrtf(fmaxf(2.0f * CBIAS - dp, 1e-12f));
            float dan = sqrtf(fmaxf(2.0f * CBIAS - dn, 1e-12f));
            st += (double)fmaxf(dap - dan + 0.3f, 0.0f);
            sc += (double)g_ce[a];
        }
#pragma unroll
        for (int o = 16; o; o >>= 1) {
            st += __shfl_down_sync(0xffffffffu, st, o);
            sc += __shfl_down_sync(0xffffffffu, sc, o);
        }
        if (lane == 0) { s_rt[wid] = st; s_rc[wid] = sc; }
        __syncthreads();
        if (tid == 0) {
            double t0 = 0.0, c0 = 0.0;
#pragma unroll
            for (int w = 0; w < 8; w++) { t0 += s_rt[w]; c0 += s_rc[w]; }
            const float LAM = 0.25f;
            const float TAU = logf(128.0f);
            float ce = (float)(c0 / (double)B_SZ);
            float l  = (float)(t0 / (double)B_SZ);
            float e1 = expf(1.0f);
            float z = 0.5f * fmaxf(-2.0f / e1, (l - TAU) / LAM);
            float pv = sqrtf(fmaxf(2.0f * (e1 * z + 1.0f), 0.0f));
            float wn = -1.0f + pv - pv * pv * (1.0f / 3.0f) + (11.0f / 72.0f) * pv * pv * pv;
            float w = (z < 0.0f) ? wn : log1pf(fmaxf(z, 0.0f));
#pragma unroll
            for (int it = 0; it < 8; it++) {
                float ew = expf(w);
                float f = fmaf(w, ew, -z);
                float wp1 = w + 1.0f;
                w = w - f / (ew * wp1 - (w + 2.0f) * f / (2.0f * wp1));
            }
            float sigma = expf(-w);
            float ls = logf(sigma);
            float loss = (ce - TAU) * sigma + LAM * ls * ls;
            out[0] = loss / (float)B_SZ;
        }
    }
}

extern "C" void kernel_launch(void* const* d_in, const int* in_sizes, int n_in,
                              void* d_out, int out_size) {
    const float* logits = (const float*)d_in[0];
    const void* targets = d_in[1];
    float* out = (float*)d_out;
    (void)in_sizes; (void)n_in; (void)out_size;

    const int smem_bytes = (A_ELEMS + 2 * B_ELEMS) * (int)sizeof(__half);   // 104448
    cudaFuncSetAttribute(triplet_mma_kernel, cudaFuncAttributeMaxDynamicSharedMemorySize,
                         smem_bytes);

    rowstats_kernel<<<B_SZ / 8, 256>>>(logits, targets);
    triplet_mma_kernel<<<NCTA, 256, smem_bytes>>>(targets, out);
}

// round 17
// speedup vs baseline: 1.2182x; 1.0386x over previous
#include <cuda_runtime.h>
#include <cuda_fp16.h>
#include <math.h>
#include <stdint.h>

#define B_SZ 8192
#define D_SZ 128
#define RM 256                           // anchor rows per CTA tile (two 128-strips)
#define TN 64                            // cols per tile
#define S_PAIRS (B_SZ / RM)              // 32 strip-pairs
#define NJ (B_SZ / TN)                   // 128 col tiles
#define TILES_TOT 2112                   // sum_{p<32} (128-4p)
#define NCTA 296                         // 2 CTAs / SM
#define BSTRIDE_H 136
#define A_ELEMS (RM * BSTRIDE_H)
#define B_ELEMS (TN * BSTRIDE_H)

__device__ __half   g_xh[B_SZ * D_SZ];
__device__ float    g_sq[B_SZ];
__device__ float    g_ce[B_SZ];
__device__ unsigned g_pm[B_SZ];          // order-encoded float max (pos candidates)
__device__ unsigned g_pn[B_SZ];          // order-encoded float min (neg candidates)
__device__ unsigned g_done;

// ---------------- helpers ----------------
__device__ __forceinline__ unsigned encf(float f) {
    unsigned u = __float_as_uint(f);
    return ((int)u < 0) ? ~u : (u | 0x80000000u);
}
__device__ __forceinline__ float decf(unsigned u) {
    return (u & 0x80000000u) ? __uint_as_float(u & 0x7fffffffu) : __uint_as_float(~u);
}
__device__ __forceinline__ void mma_f16(float d[4], const unsigned a[4],
                                        unsigned b0, unsigned b1) {
    asm volatile(
        "mma.sync.aligned.m16n8k16.row.col.f32.f16.f16.f32 "
        "{%0,%1,%2,%3}, {%4,%5,%6,%7}, {%8,%9}, {%0,%1,%2,%3};"
        : "+f"(d[0]), "+f"(d[1]), "+f"(d[2]), "+f"(d[3])
        : "r"(a[0]), "r"(a[1]), "r"(a[2]), "r"(a[3]), "r"(b0), "r"(b1));
}
__device__ __forceinline__ void ldsm_x4(unsigned& r0, unsigned& r1, unsigned& r2, unsigned& r3,
                                        unsigned addr) {
    asm volatile("ldmatrix.sync.aligned.m8n8.x4.shared.b16 {%0,%1,%2,%3}, [%4];"
                 : "=r"(r0), "=r"(r1), "=r"(r2), "=r"(r3) : "r"(addr));
}
__device__ __forceinline__ unsigned smem_u32(const void* p) {
    unsigned a;
    asm("{ .reg .u64 t; cvta.to.shared.u64 t, %1; cvt.u32.u64 %0, t; }" : "=r"(a) : "l"(p));
    return a;
}
__device__ __forceinline__ void cp16(unsigned dst, const void* src) {
    asm volatile("cp.async.cg.shared.global [%0], [%1], 16;" :: "r"(dst), "l"(src) : "memory");
}
#define CP_COMMIT() asm volatile("cp.async.commit_group;" ::: "memory")
#define CP_WAIT1()  asm volatile("cp.async.wait_group 1;" ::: "memory")
#define CP_WAIT0()  asm volatile("cp.async.wait_group 0;" ::: "memory")

// ---------- K1: sum-of-squares + CE + fp16 copy + minmax init (inline detect) ----------
__global__ void rowstats_kernel(const float* __restrict__ logits, const void* __restrict__ targets) {
    __shared__ unsigned s_det[2];
    int tid = threadIdx.x;
    int lane = tid & 31;
    int wid = tid >> 5;
    int row = (blockIdx.x << 3) + wid;
    if (blockIdx.x == 0 && tid == 0) g_done = 0u;

    {
        unsigned dv = 0;
        if (tid < 64)
            dv = (unsigned)((const int*)targets)[2 * (((blockIdx.x << 3) + tid) & (B_SZ - 1)) + 1];
#pragma unroll
        for (int o = 16; o; o >>= 1) dv |= __shfl_xor_sync(0xffffffffu, dv, o);
        if (wid < 2 && lane == 0) s_det[wid] = dv;
    }
    float4 v = reinterpret_cast<const float4*>(logits)[row * 32 + lane];
    {
        __half2 h0 = __floats2half2_rn(v.x, v.y);
        __half2 h1 = __floats2half2_rn(v.z, v.w);
        reinterpret_cast<uint2*>(g_xh)[row * 32 + lane] =
            make_uint2(*reinterpret_cast<unsigned*>(&h0), *reinterpret_cast<unsigned*>(&h1));
    }
    __syncthreads();
    const int is64 = ((s_det[0] | s_det[1]) == 0) ? 1 : 0;

    float ss = fmaf(v.x, v.x, fmaf(v.y, v.y, fmaf(v.z, v.z, v.w * v.w)));
    float mx = fmaxf(fmaxf(v.x, v.y), fmaxf(v.z, v.w));
#pragma unroll
    for (int o = 16; o; o >>= 1) {
        ss += __shfl_xor_sync(0xffffffffu, ss, o);
        mx = fmaxf(mx, __shfl_xor_sync(0xffffffffu, mx, o));
    }
    float se = expf(v.x - mx) + expf(v.y - mx) + expf(v.z - mx) + expf(v.w - mx);
#pragma unroll
    for (int o = 16; o; o >>= 1) se += __shfl_xor_sync(0xffffffffu, se, o);
    int t = is64 ? (int)((const long long*)targets)[row] : ((const int*)targets)[row];
    int c = t & 3;
    float tv = (c == 0) ? v.x : (c == 1) ? v.y : (c == 2) ? v.z : v.w;
    tv = __shfl_sync(0xffffffffu, tv, t >> 2);
    if (lane == 0) {
        g_sq[row] = ss;
        g_ce[row] = mx + logf(se) - tv;
        g_pm[row] = 0u;             // encode-min
        g_pn[row] = 0xFFFFFFFFu;    // encode-max
    }
}

// ---------- K2: symmetric fp16 MMA Gram (256x64 tiles) + mining + fused finalize ----------
// 296 CTAs (occ 2): 2112 tiles = 296*7 + 40. Warp grid 4x2: warp tile 64x32.
// Taller tiles halve the per-tile col-flush shuffles vs 128x128.
extern __shared__ __half s_all[];   // A: [0,A) ; B0: [A,A+B) ; B1: [A+B,A+2B)

__global__ void __launch_bounds__(256, 2)
triplet_mma_kernel(const void* __restrict__ targets, float* __restrict__ out) {
    __shared__ __align__(16) uint2 s_sjt[2][TN];   // {sq_j bits, t_j}
    __shared__ int    s_ta[RM];
    __shared__ float  s_sqa[RM];
    __shared__ double s_rt[8], s_rc[8];
    __shared__ int    s_last;
    __shared__ unsigned s_det;

    const int tid  = threadIdx.x;
    const int lane = tid & 31;
    const int wid  = tid >> 5;
    const int warp_m = (wid & 3) * 64;    // 4 m-warps over 256 rows
    const int warp_n = (wid >> 2) * 32;   // 2 n-warps over 64 cols
    const int g = lane >> 2, tq = lane & 3;
    const unsigned sbase = smem_u32(s_all);

    if (wid == 0) {
        unsigned dv = (unsigned)((const int*)targets)[2 * lane + 1]
                    | (unsigned)((const int*)targets)[2 * (lane + 32) + 1];
#pragma unroll
        for (int o = 16; o; o >>= 1) dv |= __shfl_xor_sync(0xffffffffu, dv, o);
        if (lane == 0) s_det = dv;
    }
    __syncthreads();
    const int is64 = (s_det == 0) ? 1 : 0;

    const unsigned a_lm = sbase + (unsigned)((warp_m + (lane & 15)) * BSTRIDE_H + (lane >> 4) * 8) * 2u;
    const unsigned b_lm_off = (unsigned)((warp_n + (lane & 7) + 8 * (lane >> 4)) * BSTRIDE_H
                                         + ((lane >> 3) & 1) * 8) * 2u;

    // ---- tile range: 2112 = 296*7 + 40 (first 40 CTAs take one extra) ----
    const int bx = blockIdx.x;
    const int my_tpc = 7 + (bx < 40 ? 1 : 0);
    int T0 = bx * 7 + (bx < 40 ? bx : 40);
    int ti = 0, rem = T0;
    while (rem >= NJ - 4 * ti) { rem -= NJ - 4 * ti; ti++; }
    int tj = 4 * ti + rem;

    __half* s_a = s_all;

    {
        const uint4* Xu = reinterpret_cast<const uint4*>(g_xh);
        for (int e = tid; e < RM * 16; e += 256) {
            int n = e >> 4, q = e & 15;
            *reinterpret_cast<uint4*>(&s_a[n * BSTRIDE_H + q * 8]) = Xu[(ti * RM + n) * 16 + q];
        }
        {
            int r = ti * RM + tid;
            s_ta[tid] = is64 ? (int)((const long long*)targets)[r] : ((const int*)targets)[r];
            s_sqa[tid] = g_sq[r];
        }
    }
    {
        int j0 = tj * TN;
        unsigned sb = sbase + (unsigned)A_ELEMS * 2u;
        for (int e = tid; e < TN * 16; e += 256) {
            int n = e >> 4, q = e & 15;
            cp16(sb + (unsigned)(n * BSTRIDE_H + q * 8) * 2u, &g_xh[(j0 + n) * D_SZ + q * 8]);
        }
        if (tid < TN) {
            int t = is64 ? (int)((const long long*)targets)[j0 + tid]
                         : ((const int*)targets)[j0 + tid];
            s_sjt[0][tid] = make_uint2(__float_as_uint(g_sq[j0 + tid]), (unsigned)t);
        }
        CP_COMMIT();
    }
    __syncthreads();

    int   ta2[4][2];
    float sqa8[8];
    int reg_i = ti;
#pragma unroll
    for (int mf = 0; mf < 4; mf++)
#pragma unroll
        for (int h = 0; h < 2; h++) {
            int r = warp_m + mf * 16 + g + 8 * h;
            ta2[mf][h] = s_ta[r];
            sqa8[2 * mf + h] = s_sqa[r];
        }

    float runm[8], runn[8];
#pragma unroll
    for (int s = 0; s < 8; s++) { runm[s] = -INFINITY; runn[s] = INFINITY; }

    for (int t = 0; t < my_tpc; t++) {
        const int cur = t & 1, nxt = cur ^ 1;
        int ni = ti, nj = tj + 1;
        if (nj == NJ) { ni = ti + 1; nj = 4 * ni; }
        const bool last = (t == my_tpc - 1);
        const bool rowchg = (!last) && (ni != ti);
        const bool diag = (tj < 4 * ti + 4);   // col range within row range

        if (reg_i != ti) {
            reg_i = ti;
#pragma unroll
            for (int mf = 0; mf < 4; mf++)
#pragma unroll
                for (int h = 0; h < 2; h++) {
                    int r = warp_m + mf * 16 + g + 8 * h;
                    ta2[mf][h] = s_ta[r];
                    sqa8[2 * mf + h] = s_sqa[r];
                }
        }

        if (!last) {
            int j0 = nj * TN;
            unsigned sb = sbase + (unsigned)(A_ELEMS + nxt * B_ELEMS) * 2u;
            for (int e = tid; e < TN * 16; e += 256) {
                int n = e >> 4, q = e & 15;
                cp16(sb + (unsigned)(n * BSTRIDE_H + q * 8) * 2u, &g_xh[(j0 + n) * D_SZ + q * 8]);
            }
            if (tid < TN) {
                int tt = is64 ? (int)((const long long*)targets)[j0 + tid]
                              : ((const int*)targets)[j0 + tid];
                s_sjt[nxt][tid] = make_uint2(__float_as_uint(g_sq[j0 + tid]), (unsigned)tt);
            }
            CP_COMMIT();
            CP_WAIT1();
        } else {
            CP_WAIT0();
        }
        __syncthreads();

        // ---- MMA 64x32 warp tile over K=128 ----
        float d[4][4][4];
#pragma unroll
        for (int mf = 0; mf < 4; mf++)
#pragma unroll
            for (int nf = 0; nf < 4; nf++)
#pragma unroll
                for (int r = 0; r < 4; r++) d[mf][nf][r] = 0.0f;

        const unsigned b_lm = sbase + (unsigned)(A_ELEMS + cur * B_ELEMS) * 2u + b_lm_off;
#pragma unroll
        for (int s = 0; s < 8; s++) {
            unsigned af[4][4];
#pragma unroll
            for (int mf = 0; mf < 4; mf++)
                ldsm_x4(af[mf][0], af[mf][1], af[mf][2], af[mf][3],
                        a_lm + mf * (16 * BSTRIDE_H * 2) + s * 32);
            unsigned bf[4][2];
#pragma unroll
            for (int u = 0; u < 2; u++)
                ldsm_x4(bf[2 * u][0], bf[2 * u][1], bf[2 * u + 1][0], bf[2 * u + 1][1],
                        b_lm + u * (16 * BSTRIDE_H * 2) + s * 32);
#pragma unroll
            for (int mf = 0; mf < 4; mf++)
#pragma unroll
                for (int nf = 0; nf < 4; nf++)
                    mma_f16(d[mf][nf], af[mf], bf[nf][0], bf[nf][1]);
        }

        // ---- two-sided epilogue (col side skipped on diagonal-block tiles) ----
        const int j0 = tj * TN;
#pragma unroll
        for (int nf = 0; nf < 4; nf++) {
            int colp = warp_n + nf * 8 + 2 * tq;
            uint4 pjt = *reinterpret_cast<const uint4*>(&s_sjt[cur][colp]);
            float sq0 = __uint_as_float(pjt.x); int t0 = (int)pjt.y;
            float sq1 = __uint_as_float(pjt.z); int t1 = (int)pjt.w;
            if (!diag) {
                float cm0 = -INFINITY, cm1 = -INFINITY, cn0 = INFINITY, cn1 = INFINITY;
#pragma unroll
                for (int mf = 0; mf < 4; mf++) {
                    int s0 = 2 * mf, s1 = 2 * mf + 1;
                    {
                        float vr = fmaf(-2.0f, d[mf][nf][0], sq0);
                        float vc = fmaf(-2.0f, d[mf][nf][0], sqa8[s0]);
                        if (t0 == ta2[mf][0]) { runm[s0] = fmaxf(runm[s0], vr); cm0 = fmaxf(cm0, vc); }
                        else                  { runn[s0] = fminf(runn[s0], vr); cn0 = fminf(cn0, vc); }
                    }
                    {
                        float vr = fmaf(-2.0f, d[mf][nf][1], sq1);
                        float vc = fmaf(-2.0f, d[mf][nf][1], sqa8[s0]);
                        if (t1 == ta2[mf][0]) { runm[s0] = fmaxf(runm[s0], vr); cm1 = fmaxf(cm1, vc); }
                        else                  { runn[s0] = fminf(runn[s0], vr); cn1 = fminf(cn1, vc); }
                    }
                    {
                        float vr = fmaf(-2.0f, d[mf][nf][2], sq0);
                        float vc = fmaf(-2.0f, d[mf][nf][2], sqa8[s1]);
                        if (t0 == ta2[mf][1]) { runm[s1] = fmaxf(runm[s1], vr); cm0 = fmaxf(cm0, vc); }
                        else                  { runn[s1] = fminf(runn[s1], vr); cn0 = fminf(cn0, vc); }
                    }
                    {
                        float vr = fmaf(-2.0f, d[mf][nf][3], sq1);
                        float vc = fmaf(-2.0f, d[mf][nf][3], sqa8[s1]);
                        if (t1 == ta2[mf][1]) { runm[s1] = fmaxf(runm[s1], vr); cm1 = fmaxf(cm1, vc); }
                        else                  { runn[s1] = fminf(runn[s1], vr); cn1 = fminf(cn1, vc); }
                    }
                }
                cm0 = fmaxf(cm0, __shfl_xor_sync(0xffffffffu, cm0, 4));
                cm0 = fmaxf(cm0, __shfl_xor_sync(0xffffffffu, cm0, 8));
                cm0 = fmaxf(cm0, __shfl_xor_sync(0xffffffffu, cm0, 16));
                cn0 = fminf(cn0, __shfl_xor_sync(0xffffffffu, cn0, 4));
                cn0 = fminf(cn0, __shfl_xor_sync(0xffffffffu, cn0, 8));
                cn0 = fminf(cn0, __shfl_xor_sync(0xffffffffu, cn0, 16));
                cm1 = fmaxf(cm1, __shfl_xor_sync(0xffffffffu, cm1, 4));
                cm1 = fmaxf(cm1, __shfl_xor_sync(0xffffffffu, cm1, 8));
                cm1 = fmaxf(cm1, __shfl_xor_sync(0xffffffffu, cm1, 16));
                cn1 = fminf(cn1, __shfl_xor_sync(0xffffffffu, cn1, 4));
                cn1 = fminf(cn1, __shfl_xor_sync(0xffffffffu, cn1, 8));
                cn1 = fminf(cn1, __shfl_xor_sync(0xffffffffu, cn1, 16));
                if (lane < 4) {
                    int gc = j0 + warp_n + nf * 8 + 2 * lane;
                    atomicMax(&g_pm[gc], encf(cm0));
                    atomicMin(&g_pn[gc], encf(cn0));
                    atomicMax(&g_pm[gc + 1], encf(cm1));
                    atomicMin(&g_pn[gc + 1], encf(cn1));
                }
            } else {
#pragma unroll
                for (int mf = 0; mf < 4; mf++) {
                    int s0 = 2 * mf, s1 = 2 * mf + 1;
                    {
                        float vr = fmaf(-2.0f, d[mf][nf][0], sq0);
                        if (t0 == ta2[mf][0]) runm[s0] = fmaxf(runm[s0], vr);
                        else                  runn[s0] = fminf(runn[s0], vr);
                    }
                    {
                        float vr = fmaf(-2.0f, d[mf][nf][1], sq1);
                        if (t1 == ta2[mf][0]) runm[s0] = fmaxf(runm[s0], vr);
                        else                  runn[s0] = fminf(runn[s0], vr);
                    }
                    {
                        float vr = fmaf(-2.0f, d[mf][nf][2], sq0);
                        if (t0 == ta2[mf][1]) runm[s1] = fmaxf(runm[s1], vr);
                        else                  runn[s1] = fminf(runn[s1], vr);
                    }
                    {
                        float vr = fmaf(-2.0f, d[mf][nf][3], sq1);
                        if (t1 == ta2[mf][1]) runm[s1] = fmaxf(runm[s1], vr);
                        else                  runn[s1] = fminf(runn[s1], vr);
                    }
                }
            }
        }

        // ---- row flush on strip-pair change / end ----
        if (last || rowchg) {
            const int i0 = ti * RM;
#pragma unroll
            for (int slot = 0; slot < 8; slot++) {
                float m = runm[slot], n = runn[slot];
                m = fmaxf(m, __shfl_xor_sync(0xffffffffu, m, 1));
                m = fmaxf(m, __shfl_xor_sync(0xffffffffu, m, 2));
                n = fminf(n, __shfl_xor_sync(0xffffffffu, n, 1));
                n = fminf(n, __shfl_xor_sync(0xffffffffu, n, 2));
                if (tq == 0) {
                    int r = i0 + warp_m + (slot >> 1) * 16 + g + 8 * (slot & 1);
                    atomicMax(&g_pm[r], encf(m));
                    atomicMin(&g_pn[r], encf(n));
                }
                runm[slot] = -INFINITY; runn[slot] = INFINITY;
            }
        }
        if (rowchg) {
            __syncthreads();
            const uint4* Xu = reinterpret_cast<const uint4*>(g_xh);
            for (int e = tid; e < RM * 16; e += 256) {
                int n = e >> 4, q = e & 15;
                *reinterpret_cast<uint4*>(&s_a[n * BSTRIDE_H + q * 8]) = Xu[(ni * RM + n) * 16 + q];
            }
            {
                int r = ni * RM + tid;
                s_ta[tid] = is64 ? (int)((const long long*)targets)[r] : ((const int*)targets)[r];
                s_sqa[tid] = g_sq[r];
            }
        }
        __syncthreads();
        ti = ni; tj = nj;
    }

    // ---- last-CTA fused finalize ----
    if (tid == 0) {
        __threadfence();
        unsigned tk = atomicAdd(&g_done, 1u);
        s_last = (tk == NCTA - 1) ? 1 : 0;
    }
    __syncthreads();
    if (s_last) {
        __threadfence();
        double st = 0.0, sc = 0.0;
#pragma unroll
        for (int a = tid; a < B_SZ; a += 256) {
            float m = decf(g_pm[a]);
            float n = decf(g_pn[a]);
            float sqi = g_sq[a];
            float dap = sqrtf(fmaxf(sqi + m, 1e-12f));
            float dan = sqrtf(fmaxf(sqi + n, 1e-12f));
            st += (double)fmaxf(dap - dan + 0.3f, 0.0f);
            sc += (double)g_ce[a];
        }
#pragma unroll
        for (int o = 16; o; o >>= 1) {
            st += __shfl_down_sync(0xffffffffu, st, o);
            sc += __shfl_down_sync(0xffffffffu, sc, o);
        }
        if (lane == 0) { s_rt[wid] = st; s_rc[wid] = sc; }
        __syncthreads();
        if (tid == 0) {
            double t0 = 0.0, c0 = 0.0;
#pragma unroll
            for (int w = 0; w < 8; w++) { t0 += s_rt[w]; c0 += s_rc[w]; }
            const float LAM = 0.25f;
            const float TAU = logf(128.0f);
            float ce = (float)(c0 / (double)B_SZ);
            float l  = (float)(t0 / (double)B_SZ);
            float e1 = expf(1.0f);
            float z = 0.5f * fmaxf(-2.0f / e1, (l - TAU) / LAM);
            float pv = sqrtf(fmaxf(2.0f * (e1 * z + 1.0f), 0.0f));
            float wn = -1.0f + pv - pv * pv * (1.0f / 3.0f) + (11.0f / 72.0f) * pv * pv * pv;
            float w = (z < 0.0f) ? wn : log1pf(fmaxf(z, 0.0f));
#pragma unroll
            for (int it = 0; it < 8; it++) {
                float ew = expf(w);
                float f = fmaf(w, ew, -z);
                float wp1 = w + 1.0f;
                w = w - f / (ew * wp1 - (w + 2.0f) * f / (2.0f * wp1));
            }
            float sigma = expf(-w);
            float ls = logf(sigma);
            float loss = (ce - TAU) * sigma + LAM * ls * ls;
            out[0] = loss / (float)B_SZ;
        }
    }
}

extern "C" void kernel_launch(void* const* d_in, const int* in_sizes, int n_in,
                              void* d_out, int out_size) {
    const float* logits = (const float*)d_in[0];
    const void* targets = d_in[1];
    float* out = (float*)d_out;
    (void)in_sizes; (void)n_in; (void)out_size;

    const int smem_bytes = (A_ELEMS + 2 * B_ELEMS) * (int)sizeof(__half);   // 104448
    cudaFuncSetAttribute(triplet_mma_kernel, cudaFuncAttributeMaxDynamicSharedMemorySize,
                         smem_bytes);

    rowstats_kernel<<<B_SZ / 8, 256>>>(logits, targets);
    triplet_mma_kernel<<<NCTA, 256, smem_bytes>>>(targets, out);
}